// round 7
// baseline (speedup 1.0000x reference)
#include <cuda_runtime.h>
#include <stdint.h>

#define NSIDE 48
#define PITCH 52                 // padded row stride (floats); 16B-aligned rows
#define NPIX  (NSIDE*NSIDE)      // 2304
#define MAT   (NSIDE*PITCH)      // 2496
#define CSIZE 4                  // CTAs per cluster (per batch)
#define RPC   (NSIDE/CSIZE)      // 12 rows owned per CTA
#define NTHR  288                // 12 rows x 24 col-pairs (1x2 tiles), 9 warps
#define NWARP (NTHR/32)
#define NITERS 5

__device__ __forceinline__ uint32_t smem_u32(const void* p) {
    return (uint32_t)__cvta_generic_to_shared(p);
}

__device__ __forceinline__ void st_remote(uint32_t laddr, uint32_t rank, float v) {
    uint32_t raddr;
    asm volatile("mapa.shared::cluster.u32 %0, %1, %2;"
                 : "=r"(raddr) : "r"(laddr), "r"(rank));
    asm volatile("st.shared::cluster.b32 [%0], %1;"
                 :: "r"(raddr), "r"(__float_as_uint(v)) : "memory");
}

__device__ __forceinline__ void cluster_sync_() {
    asm volatile("barrier.cluster.arrive.aligned;" ::: "memory");
    asm volatile("barrier.cluster.wait.aligned;" ::: "memory");
}

// Block-wide sum (288 threads = 9 warps)
__device__ __forceinline__ float block_sum(float v, float* red) {
    const int lane = threadIdx.x & 31;
    const int wid  = threadIdx.x >> 5;
    #pragma unroll
    for (int o = 16; o > 0; o >>= 1) v += __shfl_xor_sync(0xffffffffu, v, o);
    if (lane == 0) red[wid] = v;
    __syncthreads();
    if (wid == 0) {
        float x = (lane < NWARP) ? red[lane] : 0.0f;
        #pragma unroll
        for (int o = 16; o > 0; o >>= 1) x += __shfl_xor_sync(0xffffffffu, x, o);
        if (lane == 0) red[0] = x;
    }
    __syncthreads();
    float r = red[0];
    __syncthreads();
    return r;
}

#define FMA4(acc,a,b) (acc) = fmaf((a).x,(b).x,fmaf((a).y,(b).y,fmaf((a).z,(b).z,fmaf((a).w,(b).w,(acc)))))

// acc[0..1] += a[:] . b{0,1}[:] over k=0..47 (row-dot-row; operands symmetric
// or pre-transposed, so this is a standard matmul step)
__device__ __forceinline__ void mm1x2(const float* __restrict__ a,
                                      const float* __restrict__ b0,
                                      float acc[2]) {
    const float* b1 = b0 + PITCH;
    #pragma unroll
    for (int k = 0; k < NSIDE; k += 4) {
        float4 av = *(const float4*)(a  + k);
        float4 B0 = *(const float4*)(b0 + k);
        float4 B1 = *(const float4*)(b1 + k);
        FMA4(acc[0], av, B0);
        FMA4(acc[1], av, B1);
    }
}

__global__ void __launch_bounds__(NTHR, 1) __cluster_dims__(CSIZE, 1, 1)
sinkhorn_kernel(const float* __restrict__ img_pred,
                const float* __restrict__ img_target,
                const float* __restrict__ cm,
                float* __restrict__ out)
{
    __shared__ float G[MAT];        // exp(-c1d/eps), symmetric
    __shared__ float G2[MAT];       // G * c1d, symmetric
    __shared__ float At[MAT];       // transpose of exp(alpha) image (replicated)
    __shared__ float Bt[MAT];       // transpose of exp(beta) image  (replicated)
    __shared__ float U[RPC*PITCH];  // own rows of stage-1 result
    __shared__ float srow[NSIDE];   // row sums of G (for peeled first step)
    __shared__ float red[32];

    const int tid   = threadIdx.x;
    const int rank  = blockIdx.x & (CSIZE-1);
    const int batch = blockIdx.x / CSIZE;
    const int s1row = tid / 24;             // 0..11 local output row
    const int j0    = 2 * (tid - 24*s1row); // output col pair (0,2,...,46)
    const int ig    = rank * RPC + s1row;   // global output row

    // ---- build G, G2 from the cost_matrix input ----
    // cost_matrix[(a*48)*2304 + b*48] == ((a-b)/48)^2 (y-term of separable cost)
    for (int idx = tid; idx < NPIX; idx += NTHR) {
        int r = idx / NSIDE, c = idx - r * NSIDE;
        float cy = cm[(size_t)r * NSIDE * NPIX + (size_t)c * NSIDE];
        float g  = __expf(-100.0f * cy);     // exp(-c/EPS), EPS=0.01
        G [r*PITCH + c] = g;
        G2[r*PITCH + c] = g * cy;
    }

    // ---- normalized marginals (channel 0) ----
    const float* p = img_pred   + (size_t)batch * 3 * NPIX;
    const float* t = img_target + (size_t)batch * 3 * NPIX;
    float sp = 0.0f, st = 0.0f;
    for (int i = tid; i < NPIX; i += NTHR) { sp += p[i]; st += t[i]; }
    sp = block_sum(sp, red) + NPIX * 1e-9f;   // block_sum syncs; G now visible
    st = block_sum(st, red) + NPIX * 1e-9f;
    const float isp = 1.0f / sp, ist = 1.0f / st;

    // row sums of G for the peeled first half-step
    if (tid < NSIDE) {
        float s = 0.0f;
        #pragma unroll
        for (int q = 0; q < 12; q++) {
            float4 v = *(const float4*)(G + tid*PITCH + 4*q);
            s += (v.x + v.y) + (v.z + v.w);
        }
        srow[tid] = s;
    }

    // this thread's pixels: (ig, j0..j0+1). Scaling form of Sinkhorn:
    //   ea' = eu*ea / (ea*T + 1e-6)
    float eu[2], ev[2], ea[2], eb[2];
    #pragma unroll
    for (int c = 0; c < 2; c++) {
        int pix = ig * NSIDE + j0 + c;
        eu[c] = (p[pix] + 1e-9f) * isp;
        ev[c] = (t[pix] + 1e-9f) * ist;
        eb[c] = 1.0f;
    }
    __syncthreads();

    const float* Ga  = G  + ig*PITCH;        // stage-1 A row
    const float* Gb  = G  + j0*PITCH;        // stage-2 B rows
    const float* Ur  = U  + s1row*PITCH;     // stage-2 A row
    float* Uw = U + s1row*PITCH + j0;

    float acc[2];

    // ======== peeled first u half-step: T = G*1*G = srow_i * srow_j ========
    {
        float si = srow[ig];
        #pragma unroll
        for (int c = 0; c < 2; c++) {
            float e = __fdividef(eu[c], fmaf(si, srow[j0 + c], 1e-6f));
            ea[c] = e;
            int off = (j0 + c) * PITCH + ig;      // transposed store
            At[off] = e;
            uint32_t la = smem_u32(&At[off]);
            #pragma unroll
            for (int rr = 1; rr < CSIZE; rr++)
                st_remote(la, (uint32_t)((rank + rr) & (CSIZE-1)), e);
        }
        cluster_sync_();
    }

    #pragma unroll 1
    for (int it = 0; it < NITERS; it++) {
        // ======== v half-step: T = G * EA * G (K symmetric) ========
        acc[0] = acc[1] = 0.0f;
        mm1x2(Ga, At + j0*PITCH, acc);           // U = G * EA (At is EA^T)
        Uw[0] = acc[0]; Uw[1] = acc[1];
        __syncthreads();

        acc[0] = acc[1] = 0.0f;
        mm1x2(Ur, Gb, acc);                      // T = U * G (G symmetric)
        #pragma unroll
        for (int c = 0; c < 2; c++) {
            float e = __fdividef(ev[c] * eb[c], fmaf(eb[c], acc[c], 1e-6f));
            eb[c] = e;
            int off = (j0 + c) * PITCH + ig;
            Bt[off] = e;
            uint32_t la = smem_u32(&Bt[off]);
            #pragma unroll
            for (int rr = 1; rr < CSIZE; rr++)
                st_remote(la, (uint32_t)((rank + rr) & (CSIZE-1)), e);
        }
        cluster_sync_();

        if (it == NITERS - 1) break;             // 5th u-step not needed beyond peel+4

        // ======== u half-step: T = G * EB * G ========
        acc[0] = acc[1] = 0.0f;
        mm1x2(Ga, Bt + j0*PITCH, acc);           // U = G * EB (Bt is EB^T)
        Uw[0] = acc[0]; Uw[1] = acc[1];
        __syncthreads();

        acc[0] = acc[1] = 0.0f;
        mm1x2(Ur, Gb, acc);                      // T = U * G
        #pragma unroll
        for (int c = 0; c < 2; c++) {
            float e = __fdividef(eu[c] * ea[c], fmaf(ea[c], acc[c], 1e-6f));
            ea[c] = e;
            int off = (j0 + c) * PITCH + ig;
            At[off] = e;
            uint32_t la = smem_u32(&At[off]);
            #pragma unroll
            for (int rr = 1; rr < CSIZE; rr++)
                st_remote(la, (uint32_t)((rank + rr) & (CSIZE-1)), e);
        }
        cluster_sync_();
    }

    // ---- final cost: sum EA.*(G2*EB*G) + sum EA.*(G*EB*G2) ----
    float csum = 0.0f;

    acc[0] = acc[1] = 0.0f;
    mm1x2(G2 + ig*PITCH, Bt + j0*PITCH, acc);    // U = G2 * EB
    Uw[0] = acc[0]; Uw[1] = acc[1];
    __syncthreads();
    acc[0] = acc[1] = 0.0f;
    mm1x2(Ur, Gb, acc);                          // T1 = U * G
    #pragma unroll
    for (int c = 0; c < 2; c++) csum += ea[c] * acc[c];
    __syncthreads();

    acc[0] = acc[1] = 0.0f;
    mm1x2(Ga, Bt + j0*PITCH, acc);               // U = G * EB
    Uw[0] = acc[0]; Uw[1] = acc[1];
    __syncthreads();
    acc[0] = acc[1] = 0.0f;
    mm1x2(Ur, G2 + j0*PITCH, acc);               // T2 = U * G2
    #pragma unroll
    for (int c = 0; c < 2; c++) csum += ea[c] * acc[c];

    csum = block_sum(csum, red);

    // cluster reduction into rank 0
    if (tid == 0) {
        if (rank == 0) red[16] = csum;
        else st_remote(smem_u32(&red[16 + rank]), 0u, csum);
    }
    cluster_sync_();
    if (rank == 0 && tid == 0)
        out[batch] = red[16] + red[17] + red[18] + red[19];
}

extern "C" void kernel_launch(void* const* d_in, const int* in_sizes, int n_in,
                              void* d_out, int out_size) {
    const float* img_pred   = (const float*)d_in[0];
    const float* img_target = (const float*)d_in[1];
    const float* cm         = (const float*)d_in[2];
    float* out = (float*)d_out;

    const int B = in_sizes[0] / (3 * NPIX);   // 32
    sinkhorn_kernel<<<B * CSIZE, NTHR>>>(img_pred, img_target, cm, out);
}

// round 9
// speedup vs baseline: 1.0980x; 1.0980x over previous
#include <cuda_runtime.h>
#include <stdint.h>

#define NSIDE 48
#define PITCH 52                 // padded row stride (floats); 16B-aligned rows
#define NPIX  (NSIDE*NSIDE)      // 2304
#define MAT   (NSIDE*PITCH)      // 2496
#define CSIZE 4                  // CTAs per cluster (per batch)
#define RPC   (NSIDE/CSIZE)      // 12 rows owned per CTA
#define NTHR  384                // 12 warps, one output row per warp
#define NWARP 12
#define NITERS 5

__device__ __forceinline__ uint32_t smem_u32(const void* p) {
    return (uint32_t)__cvta_generic_to_shared(p);
}

__device__ __forceinline__ void st_remote(uint32_t laddr, uint32_t rank, float v) {
    uint32_t raddr;
    asm volatile("mapa.shared::cluster.u32 %0, %1, %2;"
                 : "=r"(raddr) : "r"(laddr), "r"(rank));
    asm volatile("st.shared::cluster.b32 [%0], %1;"
                 :: "r"(raddr), "r"(__float_as_uint(v)) : "memory");
}

__device__ __forceinline__ void cluster_sync_() {
    asm volatile("barrier.cluster.arrive.aligned;" ::: "memory");
    asm volatile("barrier.cluster.wait.aligned;" ::: "memory");
}

// Block-wide sum (384 threads = 12 warps)
__device__ __forceinline__ float block_sum(float v, float* red) {
    const int lane = threadIdx.x & 31;
    const int wid  = threadIdx.x >> 5;
    #pragma unroll
    for (int o = 16; o > 0; o >>= 1) v += __shfl_xor_sync(0xffffffffu, v, o);
    if (lane == 0) red[wid] = v;
    __syncthreads();
    if (wid == 0) {
        float x = (lane < NWARP) ? red[lane] : 0.0f;
        #pragma unroll
        for (int o = 8; o > 0; o >>= 1) x += __shfl_xor_sync(0xffffffffu, x, o);
        if (lane == 0) red[0] = x;
    }
    __syncthreads();
    float r = red[0];
    __syncthreads();
    return r;
}

// dot of a register-cached 48-vector with a 48-float smem row
__device__ __forceinline__ float dot48(const float4* __restrict__ a,
                                       const float* __restrict__ b) {
    float s = 0.0f;
    #pragma unroll
    for (int q = 0; q < 12; q++) {
        float4 bv = *(const float4*)(b + 4*q);
        s = fmaf(a[q].x, bv.x, s);
        s = fmaf(a[q].y, bv.y, s);
        s = fmaf(a[q].z, bv.z, s);
        s = fmaf(a[q].w, bv.w, s);
    }
    return s;
}

__global__ void __launch_bounds__(NTHR, 1) __cluster_dims__(CSIZE, 1, 1)
sinkhorn_kernel(const float* __restrict__ img_pred,
                const float* __restrict__ img_target,
                const float* __restrict__ cm,
                float* __restrict__ out)
{
    __shared__ float G[MAT];            // exp(-c1d/eps), symmetric
    __shared__ float G2[MAT];           // G * c1d, symmetric
    __shared__ float At[MAT];           // transpose of exp(alpha) image (replicated)
    __shared__ float Bt[MAT];           // transpose of exp(beta) image  (replicated)
    __shared__ float U[NWARP][PITCH];   // one private U-row per warp
    __shared__ float srow[NSIDE];       // row sums of G (peeled first step)
    __shared__ float red[32];

    const int tid   = threadIdx.x;
    const int lane  = tid & 31;
    const int wid   = tid >> 5;             // 0..11: local row
    const int rank  = blockIdx.x & (CSIZE-1);
    const int batch = blockIdx.x / CSIZE;
    const int ig    = rank * RPC + wid;     // this warp's global output row
    const int c0    = lane;                 // first column
    const int c1    = 32 + lane;            // second column (lanes 0..15 only)
    const bool has2 = lane < 16;

    // ---- build G, G2 from the cost_matrix input ----
    // cost_matrix[(a*48)*2304 + b*48] == ((a-b)/48)^2 (y-term of separable cost)
    for (int idx = tid; idx < NPIX; idx += NTHR) {
        int r = idx / NSIDE, c = idx - r * NSIDE;
        float cy = cm[(size_t)r * NSIDE * NPIX + (size_t)c * NSIDE];
        float g  = __expf(-100.0f * cy);     // exp(-c/EPS), EPS=0.01
        G [r*PITCH + c] = g;
        G2[r*PITCH + c] = g * cy;
    }

    // ---- normalized marginals (channel 0) ----
    const float* p = img_pred   + (size_t)batch * 3 * NPIX;
    const float* t = img_target + (size_t)batch * 3 * NPIX;
    float sp = 0.0f, st = 0.0f;
    for (int i = tid; i < NPIX; i += NTHR) { sp += p[i]; st += t[i]; }
    sp = block_sum(sp, red) + NPIX * 1e-9f;   // block_sum syncs; G now visible
    st = block_sum(st, red) + NPIX * 1e-9f;
    const float isp = 1.0f / sp, ist = 1.0f / st;

    // row sums of G (for the peeled first u half-step, EB = 1)
    if (tid < NSIDE) {
        float s = 0.0f;
        #pragma unroll
        for (int q = 0; q < 12; q++) {
            float4 v = *(const float4*)(G + tid*PITCH + 4*q);
            s += (v.x + v.y) + (v.z + v.w);
        }
        srow[tid] = s;
    }

    // per-lane pixel state: pixels (ig, c0) and (ig, c1).
    // Scaling form of Sinkhorn: ea' = eu*ea / (ea*T + 1e-6)
    float eu0 = (p[ig*NSIDE + c0] + 1e-9f) * isp;
    float ev0 = (t[ig*NSIDE + c0] + 1e-9f) * ist;
    float eu1 = 0.0f, ev1 = 0.0f;
    if (has2) {
        eu1 = (p[ig*NSIDE + c1] + 1e-9f) * isp;
        ev1 = (t[ig*NSIDE + c1] + 1e-9f) * ist;
    }
    float ea0 = 1.0f, ea1 = 1.0f, eb0 = 1.0f, eb1 = 1.0f;
    __syncthreads();

    // cache this warp's G row (loop-invariant)
    float4 Gr[12];
    #pragma unroll
    for (int q = 0; q < 12; q++)
        Gr[q] = *(const float4*)(G + ig*PITCH + 4*q);

    float* Urow = U[wid];
    float4 Uv[12];

    // helper lambdas would hurt reg alloc; write inline.

    // ======== peeled first u half-step: T = G*1*G = srow_i * srow_j ========
    {
        float si = srow[ig];
        float e0 = __fdividef(eu0, fmaf(si, srow[c0], 1e-6f));
        ea0 = e0;
        int off0 = c0 * PITCH + ig;
        At[off0] = e0;
        uint32_t la0 = smem_u32(&At[off0]);
        #pragma unroll
        for (int rr = 1; rr < CSIZE; rr++)
            st_remote(la0, (uint32_t)((rank + rr) & (CSIZE-1)), e0);
        if (has2) {
            float e1 = __fdividef(eu1, fmaf(si, srow[c1], 1e-6f));
            ea1 = e1;
            int off1 = c1 * PITCH + ig;
            At[off1] = e1;
            uint32_t la1 = smem_u32(&At[off1]);
            #pragma unroll
            for (int rr = 1; rr < CSIZE; rr++)
                st_remote(la1, (uint32_t)((rank + rr) & (CSIZE-1)), e1);
        }
        cluster_sync_();
    }

    #pragma unroll 1
    for (int it = 0; it < NITERS; it++) {
        // ======== v half-step: T = G * EA * G (K symmetric) ========
        {
            float u0 = dot48(Gr, At + c0*PITCH);
            float u1 = has2 ? dot48(Gr, At + c1*PITCH) : 0.0f;
            Urow[c0] = u0;
            if (has2) Urow[c1] = u1;
            __syncwarp();
            #pragma unroll
            for (int q = 0; q < 12; q++)
                Uv[q] = *(const float4*)(Urow + 4*q);
            float t0 = dot48(Uv, G + c0*PITCH);
            float e0 = __fdividef(ev0 * eb0, fmaf(eb0, t0, 1e-6f));
            eb0 = e0;
            int off0 = c0 * PITCH + ig;
            Bt[off0] = e0;
            uint32_t la0 = smem_u32(&Bt[off0]);
            #pragma unroll
            for (int rr = 1; rr < CSIZE; rr++)
                st_remote(la0, (uint32_t)((rank + rr) & (CSIZE-1)), e0);
            if (has2) {
                float t1 = dot48(Uv, G + c1*PITCH);
                float e1 = __fdividef(ev1 * eb1, fmaf(eb1, t1, 1e-6f));
                eb1 = e1;
                int off1 = c1 * PITCH + ig;
                Bt[off1] = e1;
                uint32_t la1 = smem_u32(&Bt[off1]);
                #pragma unroll
                for (int rr = 1; rr < CSIZE; rr++)
                    st_remote(la1, (uint32_t)((rank + rr) & (CSIZE-1)), e1);
            }
            cluster_sync_();
        }

        if (it == NITERS - 1) break;   // peel supplied the extra u half-step

        // ======== u half-step: T = G * EB * G ========
        {
            float u0 = dot48(Gr, Bt + c0*PITCH);
            float u1 = has2 ? dot48(Gr, Bt + c1*PITCH) : 0.0f;
            Urow[c0] = u0;
            if (has2) Urow[c1] = u1;
            __syncwarp();
            #pragma unroll
            for (int q = 0; q < 12; q++)
                Uv[q] = *(const float4*)(Urow + 4*q);
            float t0 = dot48(Uv, G + c0*PITCH);
            float e0 = __fdividef(eu0 * ea0, fmaf(ea0, t0, 1e-6f));
            ea0 = e0;
            int off0 = c0 * PITCH + ig;
            At[off0] = e0;
            uint32_t la0 = smem_u32(&At[off0]);
            #pragma unroll
            for (int rr = 1; rr < CSIZE; rr++)
                st_remote(la0, (uint32_t)((rank + rr) & (CSIZE-1)), e0);
            if (has2) {
                float t1 = dot48(Uv, G + c1*PITCH);
                float e1 = __fdividef(eu1 * ea1, fmaf(ea1, t1, 1e-6f));
                ea1 = e1;
                int off1 = c1 * PITCH + ig;
                At[off1] = e1;
                uint32_t la1 = smem_u32(&At[off1]);
                #pragma unroll
                for (int rr = 1; rr < CSIZE; rr++)
                    st_remote(la1, (uint32_t)((rank + rr) & (CSIZE-1)), e1);
            }
            cluster_sync_();
        }
    }

    // ---- final cost: sum EA.*(G2*EB*G) + sum EA.*(G*EB*G2) over own row ----
    float csum = 0.0f;

    {   // T1 = (G2 * EB) * G
        float4 G2r[12];
        #pragma unroll
        for (int q = 0; q < 12; q++)
            G2r[q] = *(const float4*)(G2 + ig*PITCH + 4*q);
        float u0 = dot48(G2r, Bt + c0*PITCH);
        float u1 = has2 ? dot48(G2r, Bt + c1*PITCH) : 0.0f;
        Urow[c0] = u0;
        if (has2) Urow[c1] = u1;
        __syncwarp();
        #pragma unroll
        for (int q = 0; q < 12; q++)
            Uv[q] = *(const float4*)(Urow + 4*q);
        csum += ea0 * dot48(Uv, G + c0*PITCH);
        if (has2) csum += ea1 * dot48(Uv, G + c1*PITCH);
        __syncwarp();   // all lanes done reading Urow before T2 overwrites
    }
    {   // T2 = (G * EB) * G2
        float u0 = dot48(Gr, Bt + c0*PITCH);
        float u1 = has2 ? dot48(Gr, Bt + c1*PITCH) : 0.0f;
        Urow[c0] = u0;
        if (has2) Urow[c1] = u1;
        __syncwarp();
        #pragma unroll
        for (int q = 0; q < 12; q++)
            Uv[q] = *(const float4*)(Urow + 4*q);
        csum += ea0 * dot48(Uv, G2 + c0*PITCH);
        if (has2) csum += ea1 * dot48(Uv, G2 + c1*PITCH);
    }

    csum = block_sum(csum, red);

    // cluster reduction into rank 0
    if (tid == 0) {
        if (rank == 0) red[16] = csum;
        else st_remote(smem_u32(&red[16 + rank]), 0u, csum);
    }
    cluster_sync_();
    if (rank == 0 && tid == 0)
        out[batch] = red[16] + red[17] + red[18] + red[19];
}

extern "C" void kernel_launch(void* const* d_in, const int* in_sizes, int n_in,
                              void* d_out, int out_size) {
    const float* img_pred   = (const float*)d_in[0];
    const float* img_target = (const float*)d_in[1];
    const float* cm         = (const float*)d_in[2];
    float* out = (float*)d_out;

    const int B = in_sizes[0] / (3 * NPIX);   // 32
    sinkhorn_kernel<<<B * CSIZE, NTHR>>>(img_pred, img_target, cm, out);
}

// round 10
// speedup vs baseline: 1.1560x; 1.0528x over previous
#include <cuda_runtime.h>
#include <stdint.h>

#define NSIDE 48
#define PITCH 52                 // padded row stride (floats); 16B-aligned rows
#define NPIX  (NSIDE*NSIDE)      // 2304
#define MAT   (NSIDE*PITCH)      // 2496
#define CSIZE 4                  // CTAs per cluster (per batch)
#define RPC   (NSIDE/CSIZE)      // 12 rows owned per CTA
#define NTHR  192
#define NWARP (NTHR/32)
#define NITERS 5

__device__ __forceinline__ uint32_t smem_u32(const void* p) {
    return (uint32_t)__cvta_generic_to_shared(p);
}

__device__ __forceinline__ uint32_t mapa_u32(uint32_t laddr, uint32_t rank) {
    uint32_t raddr;
    asm volatile("mapa.shared::cluster.u32 %0, %1, %2;"
                 : "=r"(raddr) : "r"(laddr), "r"(rank));
    return raddr;
}

__device__ __forceinline__ void st_cluster(uint32_t raddr, float v) {
    asm volatile("st.shared::cluster.b32 [%0], %1;"
                 :: "r"(raddr), "r"(__float_as_uint(v)) : "memory");
}

__device__ __forceinline__ void cluster_sync_() {
    asm volatile("barrier.cluster.arrive.aligned;" ::: "memory");
    asm volatile("barrier.cluster.wait.aligned;" ::: "memory");
}

// mbarrier arrive with cluster-scope release on a mapped (shared::cluster) address
__device__ __forceinline__ void mbar_arrive_cluster(uint32_t raddr) {
    asm volatile("mbarrier.arrive.release.cluster.shared::cluster.b64 _, [%0];"
                 :: "r"(raddr) : "memory");
}

// wait on local mbarrier for given phase parity, cluster-scope acquire
__device__ __forceinline__ void mbar_wait_acq(uint32_t mbar, uint32_t parity) {
    uint32_t done;
    asm volatile(
        "{\n\t.reg .pred p;\n\t"
        "mbarrier.try_wait.parity.acquire.cluster.shared::cta.b64 p, [%1], %2;\n\t"
        "selp.b32 %0, 1, 0, p;\n\t}"
        : "=r"(done) : "r"(mbar), "r"(parity) : "memory");
    if (!done) {
        asm volatile(
            "{\n\t.reg .pred P1;\n\t"
            "WL_%=:\n\t"
            "mbarrier.try_wait.parity.acquire.cluster.shared::cta.b64 P1, [%0], %1, 0x989680;\n\t"
            "@P1 bra.uni WD_%=;\n\t"
            "bra.uni WL_%=;\n\t"
            "WD_%=:\n\t}"
            :: "r"(mbar), "r"(parity) : "memory");
    }
}

// Block-wide sum (192 threads = 6 warps)
__device__ __forceinline__ float block_sum(float v, float* red) {
    const int lane = threadIdx.x & 31;
    const int wid  = threadIdx.x >> 5;
    #pragma unroll
    for (int o = 16; o > 0; o >>= 1) v += __shfl_xor_sync(0xffffffffu, v, o);
    if (lane == 0) red[wid] = v;
    __syncthreads();
    if (wid == 0) {
        float x = (lane < NWARP) ? red[lane] : 0.0f;
        #pragma unroll
        for (int o = 4; o > 0; o >>= 1) x += __shfl_xor_sync(0xffffffffu, x, o);
        if (lane == 0) red[0] = x;
    }
    __syncthreads();
    float r = red[0];
    __syncthreads();
    return r;
}

#define FMA4(acc,a,b) (acc) = fmaf((a).x,(b).x,fmaf((a).y,(b).y,fmaf((a).z,(b).z,fmaf((a).w,(b).w,(acc)))))

// acc[0..2] += a[:] . b{0,1,2}[:] over k=0..47 (row-dot-row; operands symmetric
// or pre-transposed, so this is a standard matmul step)
__device__ __forceinline__ void mm1x3(const float* __restrict__ a,
                                      const float* __restrict__ b0,
                                      float acc[3]) {
    const float* b1 = b0 + PITCH;
    const float* b2 = b0 + 2*PITCH;
    #pragma unroll
    for (int k = 0; k < NSIDE; k += 4) {
        float4 av = *(const float4*)(a  + k);
        float4 B0 = *(const float4*)(b0 + k);
        float4 B1 = *(const float4*)(b1 + k);
        float4 B2 = *(const float4*)(b2 + k);
        FMA4(acc[0], av, B0);
        FMA4(acc[1], av, B1);
        FMA4(acc[2], av, B2);
    }
}

__global__ void __launch_bounds__(NTHR, 1) __cluster_dims__(CSIZE, 1, 1)
sinkhorn_kernel(const float* __restrict__ img_pred,
                const float* __restrict__ img_target,
                const float* __restrict__ cm,
                float* __restrict__ out)
{
    __shared__ float G[MAT];        // exp(-c1d/eps), symmetric
    __shared__ float G2[MAT];       // G * c1d, symmetric
    __shared__ float At[MAT];       // transpose of exp(alpha) image (replicated)
    __shared__ float Bt[MAT];       // transpose of exp(beta) image  (replicated)
    __shared__ float U[RPC*PITCH];  // own rows of stage-1 result
    __shared__ float srow[NSIDE];   // row sums of G (peeled first step)
    __shared__ float red[24];
    __shared__ unsigned long long mbar;   // 4-arrival cluster handshake barrier

    const int tid   = threadIdx.x;
    const int rank  = blockIdx.x & (CSIZE-1);
    const int batch = blockIdx.x / CSIZE;
    const int s1row = tid >> 4;             // 0..11 local output row
    const int j0    = 3 * (tid & 15);       // output col group
    const int ig    = rank * RPC + s1row;   // global output row

    const uint32_t mb_local = smem_u32(&mbar);
    // mapped addresses (computed once): peer mirror bases + all 4 mbar addrs
    uint32_t pAt[CSIZE-1], pBt[CSIZE-1], mbAll[CSIZE];
    {
        uint32_t atb = smem_u32(At), btb = smem_u32(Bt);
        #pragma unroll
        for (int rr = 1; rr < CSIZE; rr++) {
            uint32_t r = (uint32_t)((rank + rr) & (CSIZE-1));
            pAt[rr-1] = mapa_u32(atb, r);
            pBt[rr-1] = mapa_u32(btb, r);
        }
        #pragma unroll
        for (int r = 0; r < CSIZE; r++)
            mbAll[r] = mapa_u32(mb_local, (uint32_t)r);
    }
    if (tid == 0) {
        asm volatile("mbarrier.init.shared.b64 [%0], %1;"
                     :: "r"(mb_local), "r"((uint32_t)CSIZE) : "memory");
    }

    // ---- build G, G2 from the cost_matrix input ----
    // cost_matrix[(a*48)*2304 + b*48] == ((a-b)/48)^2 (y-term of separable cost)
    for (int idx = tid; idx < NPIX; idx += NTHR) {
        int r = idx / NSIDE, c = idx - r * NSIDE;
        float cy = cm[(size_t)r * NSIDE * NPIX + (size_t)c * NSIDE];
        float g  = __expf(-100.0f * cy);     // exp(-c/EPS), EPS=0.01
        G [r*PITCH + c] = g;
        G2[r*PITCH + c] = g * cy;
    }

    // ---- normalized marginals (channel 0) ----
    const float* p = img_pred   + (size_t)batch * 3 * NPIX;
    const float* t = img_target + (size_t)batch * 3 * NPIX;
    float sp = 0.0f, st = 0.0f;
    for (int i = tid; i < NPIX; i += NTHR) { sp += p[i]; st += t[i]; }
    sp = block_sum(sp, red) + NPIX * 1e-9f;   // block_sum syncs; G now visible
    st = block_sum(st, red) + NPIX * 1e-9f;
    const float isp = 1.0f / sp, ist = 1.0f / st;

    // row sums of G for the peeled first u half-step (EB = 1)
    if (tid < NSIDE) {
        float s = 0.0f;
        #pragma unroll
        for (int q = 0; q < 12; q++) {
            float4 v = *(const float4*)(G + tid*PITCH + 4*q);
            s += (v.x + v.y) + (v.z + v.w);
        }
        srow[tid] = s;
    }

    // this thread's pixels: (ig, j0..j0+2). Scaling form of Sinkhorn:
    //   ea' = eu*ea / (ea*T + 1e-6)
    float eu[3], ev[3], ea[3], eb[3];
    #pragma unroll
    for (int c = 0; c < 3; c++) {
        int pix = ig * NSIDE + j0 + c;
        eu[c] = (p[pix] + 1e-9f) * isp;
        ev[c] = (t[pix] + 1e-9f) * ist;
        ea[c] = 1.0f;
        eb[c] = 1.0f;
    }
    __syncthreads();
    cluster_sync_();   // mbarrier init visible cluster-wide before any arrival

    const float* Ga = G + ig*PITCH;          // stage-1 A row
    const float* Gb = G + j0*PITCH;          // stage-2 B rows
    const float* Ur = U + s1row*PITCH;       // stage-2 A row
    float* Uw = U + s1row*PITCH + j0;

    int phase = 0;
    float acc[3];

    // handshake: all local+remote stores done -> fence -> arrive x4 -> wait
    #define HANDSHAKE() do {                                                 \
        __syncthreads();                                                     \
        if (tid == 0) {                                                      \
            asm volatile("fence.acq_rel.cluster;" ::: "memory");             \
            _Pragma("unroll")                                                \
            for (int _r = 0; _r < CSIZE; _r++) mbar_arrive_cluster(mbAll[_r]); \
        }                                                                    \
        mbar_wait_acq(mb_local, (uint32_t)(phase & 1));                      \
        phase++;                                                             \
    } while (0)

    // ======== peeled first u half-step: T = G*1*G = srow_i * srow_j ========
    {
        float si = srow[ig];
        #pragma unroll
        for (int c = 0; c < 3; c++) {
            float e = __fdividef(eu[c], fmaf(si, srow[j0 + c], 1e-6f));
            ea[c] = e;
            int boff = ((j0 + c) * PITCH + ig) * 4;     // transposed store
            *(float*)((char*)At + boff) = e;
            #pragma unroll
            for (int rr = 0; rr < CSIZE-1; rr++)
                st_cluster(pAt[rr] + boff, e);
        }
        HANDSHAKE();
    }

    #pragma unroll 1
    for (int it = 0; it < NITERS; it++) {
        // ======== v half-step: T = G * EA * G (K symmetric) ========
        acc[0]=acc[1]=acc[2]=0.0f;
        mm1x3(Ga, At + j0*PITCH, acc);           // U = G * EA (At is EA^T)
        Uw[0]=acc[0]; Uw[1]=acc[1]; Uw[2]=acc[2];
        __syncthreads();

        acc[0]=acc[1]=acc[2]=0.0f;
        mm1x3(Ur, Gb, acc);                      // T = U * G (G symmetric)
        #pragma unroll
        for (int c = 0; c < 3; c++) {
            float e = __fdividef(ev[c] * eb[c], fmaf(eb[c], acc[c], 1e-6f));
            eb[c] = e;
            int boff = ((j0 + c) * PITCH + ig) * 4;
            *(float*)((char*)Bt + boff) = e;
            #pragma unroll
            for (int rr = 0; rr < CSIZE-1; rr++)
                st_cluster(pBt[rr] + boff, e);
        }
        HANDSHAKE();

        if (it == NITERS - 1) break;             // peel supplied the 5th u-step

        // ======== u half-step: T = G * EB * G ========
        acc[0]=acc[1]=acc[2]=0.0f;
        mm1x3(Ga, Bt + j0*PITCH, acc);           // U = G * EB (Bt is EB^T)
        Uw[0]=acc[0]; Uw[1]=acc[1]; Uw[2]=acc[2];
        __syncthreads();

        acc[0]=acc[1]=acc[2]=0.0f;
        mm1x3(Ur, Gb, acc);                      // T = U * G
        #pragma unroll
        for (int c = 0; c < 3; c++) {
            float e = __fdividef(eu[c] * ea[c], fmaf(ea[c], acc[c], 1e-6f));
            ea[c] = e;
            int boff = ((j0 + c) * PITCH + ig) * 4;
            *(float*)((char*)At + boff) = e;
            #pragma unroll
            for (int rr = 0; rr < CSIZE-1; rr++)
                st_cluster(pAt[rr] + boff, e);
        }
        HANDSHAKE();
    }

    // ---- final cost: sum EA.*(G2*EB*G) + sum EA.*(G*EB*G2) ----
    float csum = 0.0f;

    acc[0]=acc[1]=acc[2]=0.0f;
    mm1x3(G2 + ig*PITCH, Bt + j0*PITCH, acc);    // U = G2 * EB
    Uw[0]=acc[0]; Uw[1]=acc[1]; Uw[2]=acc[2];
    __syncthreads();
    acc[0]=acc[1]=acc[2]=0.0f;
    mm1x3(Ur, Gb, acc);                          // T1 = U * G
    #pragma unroll
    for (int c = 0; c < 3; c++) csum += ea[c] * acc[c];
    __syncthreads();

    acc[0]=acc[1]=acc[2]=0.0f;
    mm1x3(Ga, Bt + j0*PITCH, acc);               // U = G * EB
    Uw[0]=acc[0]; Uw[1]=acc[1]; Uw[2]=acc[2];
    __syncthreads();
    acc[0]=acc[1]=acc[2]=0.0f;
    mm1x3(Ur, G2 + j0*PITCH, acc);               // T2 = U * G2
    #pragma unroll
    for (int c = 0; c < 3; c++) csum += ea[c] * acc[c];

    csum = block_sum(csum, red);

    // cluster reduction into rank 0 (heavy sync OK once at the end)
    if (tid == 0) {
        if (rank == 0) red[16] = csum;
        else st_cluster(mapa_u32(smem_u32(&red[16 + rank]), 0u), csum);
    }
    cluster_sync_();
    if (rank == 0 && tid == 0)
        out[batch] = red[16] + red[17] + red[18] + red[19];

    #undef HANDSHAKE
}

extern "C" void kernel_launch(void* const* d_in, const int* in_sizes, int n_in,
                              void* d_out, int out_size) {
    const float* img_pred   = (const float*)d_in[0];
    const float* img_target = (const float*)d_in[1];
    const float* cm         = (const float*)d_in[2];
    float* out = (float*)d_out;

    const int B = in_sizes[0] / (3 * NPIX);   // 32
    sinkhorn_kernel<<<B * CSIZE, NTHR>>>(img_pred, img_target, cm, out);
}

// round 11
// speedup vs baseline: 1.3591x; 1.1757x over previous
#include <cuda_runtime.h>
#include <stdint.h>

#define NSIDE 48
#define PITCH 52                 // padded row stride (floats); 16B-aligned rows
#define NPIX  (NSIDE*NSIDE)      // 2304
#define MAT   (NSIDE*PITCH)      // 2496
#define CSIZE 4                  // CTAs per cluster (per batch)
#define RPC   (NSIDE/CSIZE)      // 12 rows owned per CTA
#define NTHR  192
#define NWARP (NTHR/32)
#define NITERS 5

__device__ __forceinline__ uint32_t smem_u32(const void* p) {
    return (uint32_t)__cvta_generic_to_shared(p);
}

__device__ __forceinline__ void st_remote(uint32_t laddr, uint32_t rank, float v) {
    uint32_t raddr;
    asm volatile("mapa.shared::cluster.u32 %0, %1, %2;"
                 : "=r"(raddr) : "r"(laddr), "r"(rank));
    asm volatile("st.shared::cluster.b32 [%0], %1;"
                 :: "r"(raddr), "r"(__float_as_uint(v)) : "memory");
}

__device__ __forceinline__ void cluster_sync_() {
    asm volatile("barrier.cluster.arrive.aligned;" ::: "memory");
    asm volatile("barrier.cluster.wait.aligned;" ::: "memory");
}

// Block-wide sum (192 threads = 6 warps)
__device__ __forceinline__ float block_sum(float v, float* red) {
    const int lane = threadIdx.x & 31;
    const int wid  = threadIdx.x >> 5;
    #pragma unroll
    for (int o = 16; o > 0; o >>= 1) v += __shfl_xor_sync(0xffffffffu, v, o);
    if (lane == 0) red[wid] = v;
    __syncthreads();
    if (wid == 0) {
        float x = (lane < NWARP) ? red[lane] : 0.0f;
        #pragma unroll
        for (int o = 4; o > 0; o >>= 1) x += __shfl_xor_sync(0xffffffffu, x, o);
        if (lane == 0) red[0] = x;
    }
    __syncthreads();
    float r = red[0];
    __syncthreads();
    return r;
}

#define FMA4(acc,a,b) (acc) = fmaf((a).x,(b).x,fmaf((a).y,(b).y,fmaf((a).z,(b).z,fmaf((a).w,(b).w,(acc)))))

// acc[0..2] += a[:] . b{0,1,2}[:] over k=0..47 (row-dot-row; operands symmetric
// or pre-transposed, so this is a standard matmul step)
__device__ __forceinline__ void mm1x3(const float* __restrict__ a,
                                      const float* __restrict__ b0,
                                      float acc[3]) {
    const float* b1 = b0 + PITCH;
    const float* b2 = b0 + 2*PITCH;
    #pragma unroll
    for (int k = 0; k < NSIDE; k += 4) {
        float4 av = *(const float4*)(a  + k);
        float4 B0 = *(const float4*)(b0 + k);
        float4 B1 = *(const float4*)(b1 + k);
        float4 B2 = *(const float4*)(b2 + k);
        FMA4(acc[0], av, B0);
        FMA4(acc[1], av, B1);
        FMA4(acc[2], av, B2);
    }
}

__global__ void __launch_bounds__(NTHR, 1) __cluster_dims__(CSIZE, 1, 1)
sinkhorn_kernel(const float* __restrict__ img_pred,
                const float* __restrict__ img_target,
                const float* __restrict__ cm,
                float* __restrict__ out)
{
    __shared__ float G[MAT];        // exp(-c1d/eps), symmetric
    __shared__ float G2[MAT];       // G * c1d, symmetric
    __shared__ float At[MAT];       // transpose of exp(alpha) image (replicated)
    __shared__ float Bt[MAT];       // transpose of exp(beta) image  (replicated)
    __shared__ float U[RPC*PITCH];  // own rows of stage-1 result
    __shared__ float srow[NSIDE];   // row sums of G (peeled first step)
    __shared__ float red[24];

    const int tid   = threadIdx.x;
    const int rank  = blockIdx.x & (CSIZE-1);
    const int batch = blockIdx.x / CSIZE;
    const int s1row = tid >> 4;             // 0..11 local output row
    const int j0    = 3 * (tid & 15);       // output col group
    const int ig    = rank * RPC + s1row;   // global output row

    // ---- build G, G2 from the cost_matrix input ----
    // cost_matrix[(a*48)*2304 + b*48] == ((a-b)/48)^2 (y-term of separable cost)
    for (int idx = tid; idx < NPIX; idx += NTHR) {
        int r = idx / NSIDE, c = idx - r * NSIDE;
        float cy = cm[(size_t)r * NSIDE * NPIX + (size_t)c * NSIDE];
        float g  = __expf(-100.0f * cy);     // exp(-c/EPS), EPS=0.01
        G [r*PITCH + c] = g;
        G2[r*PITCH + c] = g * cy;
    }

    // ---- normalized marginals (channel 0) ----
    const float* p = img_pred   + (size_t)batch * 3 * NPIX;
    const float* t = img_target + (size_t)batch * 3 * NPIX;
    float sp = 0.0f, st = 0.0f;
    for (int i = tid; i < NPIX; i += NTHR) { sp += p[i]; st += t[i]; }
    sp = block_sum(sp, red) + NPIX * 1e-9f;   // block_sum syncs; G now visible
    st = block_sum(st, red) + NPIX * 1e-9f;
    const float isp = 1.0f / sp, ist = 1.0f / st;

    // row sums of G for the peeled first u half-step (EB = 1)
    if (tid < NSIDE) {
        float s = 0.0f;
        #pragma unroll
        for (int q = 0; q < 12; q++) {
            float4 v = *(const float4*)(G + tid*PITCH + 4*q);
            s += (v.x + v.y) + (v.z + v.w);
        }
        srow[tid] = s;
    }

    // this thread's pixels: (ig, j0..j0+2). Scaling form of Sinkhorn:
    //   ea' = eu*ea / (ea*T + 1e-6)
    float eu[3], ev[3], ea[3], eb[3];
    #pragma unroll
    for (int c = 0; c < 3; c++) {
        int pix = ig * NSIDE + j0 + c;
        eu[c] = (p[pix] + 1e-9f) * isp;
        ev[c] = (t[pix] + 1e-9f) * ist;
        ea[c] = 1.0f;
        eb[c] = 1.0f;
    }
    __syncthreads();

    const float* Ga = G + ig*PITCH;          // stage-1 A row
    const float* Gb = G + j0*PITCH;          // stage-2 B rows
    const float* Ur = U + s1row*PITCH;       // stage-2 A row
    float* Uw = U + s1row*PITCH + j0;

    float acc[3];

    // ======== peeled first u half-step: T = G*1*G = srow_i * srow_j ========
    {
        float si = srow[ig];
        #pragma unroll
        for (int c = 0; c < 3; c++) {
            float e = __fdividef(eu[c], fmaf(si, srow[j0 + c], 1e-6f));
            ea[c] = e;
            int off = (j0 + c) * PITCH + ig;      // transposed store
            At[off] = e;
            uint32_t la = smem_u32(&At[off]);
            #pragma unroll
            for (int rr = 1; rr < CSIZE; rr++)
                st_remote(la, (uint32_t)((rank + rr) & (CSIZE-1)), e);
        }
        cluster_sync_();
    }

    #pragma unroll 1
    for (int it = 0; it < NITERS; it++) {
        // ======== v half-step: T = G * EA * G (K symmetric) ========
        acc[0]=acc[1]=acc[2]=0.0f;
        mm1x3(Ga, At + j0*PITCH, acc);           // U = G * EA (At is EA^T)
        Uw[0]=acc[0]; Uw[1]=acc[1]; Uw[2]=acc[2];
        __syncthreads();

        acc[0]=acc[1]=acc[2]=0.0f;
        mm1x3(Ur, Gb, acc);                      // T = U * G (G symmetric)
        #pragma unroll
        for (int c = 0; c < 3; c++) {
            float e = __fdividef(ev[c] * eb[c], fmaf(eb[c], acc[c], 1e-6f));
            eb[c] = e;
            int off = (j0 + c) * PITCH + ig;
            Bt[off] = e;
            uint32_t la = smem_u32(&Bt[off]);
            #pragma unroll
            for (int rr = 1; rr < CSIZE; rr++)
                st_remote(la, (uint32_t)((rank + rr) & (CSIZE-1)), e);
        }
        cluster_sync_();

        if (it == NITERS - 1) break;             // peel supplied the 5th u-step

        // ======== u half-step: T = G * EB * G ========
        acc[0]=acc[1]=acc[2]=0.0f;
        mm1x3(Ga, Bt + j0*PITCH, acc);           // U = G * EB (Bt is EB^T)
        Uw[0]=acc[0]; Uw[1]=acc[1]; Uw[2]=acc[2];
        __syncthreads();

        acc[0]=acc[1]=acc[2]=0.0f;
        mm1x3(Ur, Gb, acc);                      // T = U * G
        #pragma unroll
        for (int c = 0; c < 3; c++) {
            float e = __fdividef(eu[c] * ea[c], fmaf(ea[c], acc[c], 1e-6f));
            ea[c] = e;
            int off = (j0 + c) * PITCH + ig;
            At[off] = e;
            uint32_t la = smem_u32(&At[off]);
            #pragma unroll
            for (int rr = 1; rr < CSIZE; rr++)
                st_remote(la, (uint32_t)((rank + rr) & (CSIZE-1)), e);
        }
        cluster_sync_();
    }

    // ---- final cost: sum EA.*(G2*EB*G) + sum EA.*(G*EB*G2) ----
    float csum = 0.0f;

    acc[0]=acc[1]=acc[2]=0.0f;
    mm1x3(G2 + ig*PITCH, Bt + j0*PITCH, acc);    // U = G2 * EB
    Uw[0]=acc[0]; Uw[1]=acc[1]; Uw[2]=acc[2];
    __syncthreads();
    acc[0]=acc[1]=acc[2]=0.0f;
    mm1x3(Ur, Gb, acc);                          // T1 = U * G
    #pragma unroll
    for (int c = 0; c < 3; c++) csum += ea[c] * acc[c];
    __syncthreads();

    acc[0]=acc[1]=acc[2]=0.0f;
    mm1x3(Ga, Bt + j0*PITCH, acc);               // U = G * EB
    Uw[0]=acc[0]; Uw[1]=acc[1]; Uw[2]=acc[2];
    __syncthreads();
    acc[0]=acc[1]=acc[2]=0.0f;
    mm1x3(Ur, G2 + j0*PITCH, acc);               // T2 = U * G2
    #pragma unroll
    for (int c = 0; c < 3; c++) csum += ea[c] * acc[c];

    csum = block_sum(csum, red);

    // cluster reduction into rank 0
    if (tid == 0) {
        if (rank == 0) red[16] = csum;
        else st_remote(smem_u32(&red[16 + rank]), 0u, csum);
    }
    cluster_sync_();
    if (rank == 0 && tid == 0)
        out[batch] = red[16] + red[17] + red[18] + red[19];
}

extern "C" void kernel_launch(void* const* d_in, const int* in_sizes, int n_in,
                              void* d_out, int out_size) {
    const float* img_pred   = (const float*)d_in[0];
    const float* img_target = (const float*)d_in[1];
    const float* cm         = (const float*)d_in[2];
    float* out = (float*)d_out;

    const int B = in_sizes[0] / (3 * NPIX);   // 32
    sinkhorn_kernel<<<B * CSIZE, NTHR>>>(img_pred, img_target, cm, out);
}

// round 12
// speedup vs baseline: 1.4580x; 1.0727x over previous
#include <cuda_runtime.h>
#include <stdint.h>

#define NSIDE 48
#define PITCH 52                 // padded row stride (floats); 16B-aligned rows
#define NPIX  (NSIDE*NSIDE)      // 2304
#define MAT   (NSIDE*PITCH)      // 2496
#define CSIZE 4                  // CTAs per cluster (per batch)
#define RPC   (NSIDE/CSIZE)      // 12 rows owned per CTA
#define NTHR  192
#define NWARP (NTHR/32)
#define NITERS 5

__device__ __forceinline__ uint32_t smem_u32(const void* p) {
    return (uint32_t)__cvta_generic_to_shared(p);
}

__device__ __forceinline__ void st_remote(uint32_t laddr, uint32_t rank, float v) {
    uint32_t raddr;
    asm volatile("mapa.shared::cluster.u32 %0, %1, %2;"
                 : "=r"(raddr) : "r"(laddr), "r"(rank));
    asm volatile("st.shared::cluster.b32 [%0], %1;"
                 :: "r"(raddr), "r"(__float_as_uint(v)) : "memory");
}

__device__ __forceinline__ void cluster_sync_() {
    asm volatile("barrier.cluster.arrive.aligned;" ::: "memory");
    asm volatile("barrier.cluster.wait.aligned;" ::: "memory");
}

// Block-wide sum (192 threads = 6 warps)
__device__ __forceinline__ float block_sum(float v, float* red) {
    const int lane = threadIdx.x & 31;
    const int wid  = threadIdx.x >> 5;
    #pragma unroll
    for (int o = 16; o > 0; o >>= 1) v += __shfl_xor_sync(0xffffffffu, v, o);
    if (lane == 0) red[wid] = v;
    __syncthreads();
    if (wid == 0) {
        float x = (lane < NWARP) ? red[lane] : 0.0f;
        #pragma unroll
        for (int o = 4; o > 0; o >>= 1) x += __shfl_xor_sync(0xffffffffu, x, o);
        if (lane == 0) red[0] = x;
    }
    __syncthreads();
    float r = red[0];
    __syncthreads();
    return r;
}

#define FMA4(acc,a,b) (acc) = fmaf((a).x,(b).x,fmaf((a).y,(b).y,fmaf((a).z,(b).z,fmaf((a).w,(b).w,(acc)))))

// acc[0..2] += a[:] . b{0,1,2}[:] over k=0..47 (row-dot-row; operands symmetric
// or pre-transposed, so this is a standard matmul step)
__device__ __forceinline__ void mm1x3(const float* __restrict__ a,
                                      const float* __restrict__ b0,
                                      float acc[3]) {
    const float* b1 = b0 + PITCH;
    const float* b2 = b0 + 2*PITCH;
    #pragma unroll
    for (int k = 0; k < NSIDE; k += 4) {
        float4 av = *(const float4*)(a  + k);
        float4 B0 = *(const float4*)(b0 + k);
        float4 B1 = *(const float4*)(b1 + k);
        float4 B2 = *(const float4*)(b2 + k);
        FMA4(acc[0], av, B0);
        FMA4(acc[1], av, B1);
        FMA4(acc[2], av, B2);
    }
}

__global__ void __launch_bounds__(NTHR, 1) __cluster_dims__(CSIZE, 1, 1)
sinkhorn_kernel(const float* __restrict__ img_pred,
                const float* __restrict__ img_target,
                const float* __restrict__ cm,
                float* __restrict__ out)
{
    __shared__ float G[MAT];        // exp(-c1d/eps), symmetric
    __shared__ float G2[MAT];       // G * c1d, symmetric
    __shared__ float At[MAT];       // transpose of exp(alpha) image (replicated)
    __shared__ float Bt[MAT];       // transpose of exp(beta) image  (replicated)
    __shared__ float U[RPC*PITCH];  // own rows of stage-1 result
    __shared__ float srow[NSIDE];   // row sums of G (peeled first step)
    __shared__ float red[24];

    const int tid   = threadIdx.x;
    const int rank  = blockIdx.x & (CSIZE-1);
    const int batch = blockIdx.x / CSIZE;
    const int s1row = tid >> 4;             // 0..11 local output row
    const int j0    = 3 * (tid & 15);       // output col group
    const int ig    = rank * RPC + s1row;   // global output row

    // ---- build G, G2 from the cost_matrix input ----
    // cost_matrix[(a*48)*2304 + b*48] == ((a-b)/48)^2 (y-term of separable cost)
    for (int idx = tid; idx < NPIX; idx += NTHR) {
        int r = idx / NSIDE, c = idx - r * NSIDE;
        float cy = cm[(size_t)r * NSIDE * NPIX + (size_t)c * NSIDE];
        float g  = __expf(-100.0f * cy);     // exp(-c/EPS), EPS=0.01
        G [r*PITCH + c] = g;
        G2[r*PITCH + c] = g * cy;
    }

    // ---- normalized marginals (channel 0) ----
    const float* p = img_pred   + (size_t)batch * 3 * NPIX;
    const float* t = img_target + (size_t)batch * 3 * NPIX;
    float sp = 0.0f, st = 0.0f;
    for (int i = tid; i < NPIX; i += NTHR) { sp += p[i]; st += t[i]; }
    sp = block_sum(sp, red) + NPIX * 1e-9f;   // block_sum syncs; G now visible
    st = block_sum(st, red) + NPIX * 1e-9f;
    const float isp = 1.0f / sp, ist = 1.0f / st;

    // row sums of G for the peeled first u half-step (EB = 1)
    if (tid < NSIDE) {
        float s = 0.0f;
        #pragma unroll
        for (int q = 0; q < 12; q++) {
            float4 v = *(const float4*)(G + tid*PITCH + 4*q);
            s += (v.x + v.y) + (v.z + v.w);
        }
        srow[tid] = s;
    }

    // this thread's pixels: (ig, j0..j0+2). Scaling form of Sinkhorn:
    //   ea' = eu*ea / (ea*T + 1e-6)
    float eu[3], ev[3], ea[3], eb[3];
    #pragma unroll
    for (int c = 0; c < 3; c++) {
        int pix = ig * NSIDE + j0 + c;
        eu[c] = (p[pix] + 1e-9f) * isp;
        ev[c] = (t[pix] + 1e-9f) * ist;
        ea[c] = 1.0f;
        eb[c] = 1.0f;
    }
    __syncthreads();

    const float* Ga = G + ig*PITCH;          // stage-1 A row
    const float* Gb = G + j0*PITCH;          // stage-2 B rows
    const float* Ur = U + s1row*PITCH;       // stage-2 A row
    float* Uw = U + s1row*PITCH + j0;

    float acc[3];

    // NOTE on the stage-1 -> stage-2 barrier: U row r is written by threads
    // 16r..16r+15 and read in stage 2 by exactly the same 16 threads (s1row is
    // identical in both stages). Producer and consumer sets are within ONE
    // warp, so __syncwarp() (with its intra-warp memory ordering) suffices;
    // no block-wide barrier between the two stages of a half-step.

    // ======== peeled first u half-step: T = G*1*G = srow_i * srow_j ========
    {
        float si = srow[ig];
        #pragma unroll
        for (int c = 0; c < 3; c++) {
            float e = __fdividef(eu[c], fmaf(si, srow[j0 + c], 1e-6f));
            ea[c] = e;
            int off = (j0 + c) * PITCH + ig;      // transposed store
            At[off] = e;
            uint32_t la = smem_u32(&At[off]);
            #pragma unroll
            for (int rr = 1; rr < CSIZE; rr++)
                st_remote(la, (uint32_t)((rank + rr) & (CSIZE-1)), e);
        }
        cluster_sync_();
    }

    #pragma unroll 1
    for (int it = 0; it < NITERS; it++) {
        // ======== v half-step: T = G * EA * G (K symmetric) ========
        acc[0]=acc[1]=acc[2]=0.0f;
        mm1x3(Ga, At + j0*PITCH, acc);           // U = G * EA (At is EA^T)
        Uw[0]=acc[0]; Uw[1]=acc[1]; Uw[2]=acc[2];
        __syncwarp();

        acc[0]=acc[1]=acc[2]=0.0f;
        mm1x3(Ur, Gb, acc);                      // T = U * G (G symmetric)
        #pragma unroll
        for (int c = 0; c < 3; c++) {
            float e = __fdividef(ev[c] * eb[c], fmaf(eb[c], acc[c], 1e-6f));
            eb[c] = e;
            int off = (j0 + c) * PITCH + ig;
            Bt[off] = e;
            uint32_t la = smem_u32(&Bt[off]);
            #pragma unroll
            for (int rr = 1; rr < CSIZE; rr++)
                st_remote(la, (uint32_t)((rank + rr) & (CSIZE-1)), e);
        }
        __syncwarp();
        cluster_sync_();

        if (it == NITERS - 1) break;             // peel supplied the 5th u-step

        // ======== u half-step: T = G * EB * G ========
        acc[0]=acc[1]=acc[2]=0.0f;
        mm1x3(Ga, Bt + j0*PITCH, acc);           // U = G * EB (Bt is EB^T)
        Uw[0]=acc[0]; Uw[1]=acc[1]; Uw[2]=acc[2];
        __syncwarp();

        acc[0]=acc[1]=acc[2]=0.0f;
        mm1x3(Ur, Gb, acc);                      // T = U * G
        #pragma unroll
        for (int c = 0; c < 3; c++) {
            float e = __fdividef(eu[c] * ea[c], fmaf(ea[c], acc[c], 1e-6f));
            ea[c] = e;
            int off = (j0 + c) * PITCH + ig;
            At[off] = e;
            uint32_t la = smem_u32(&At[off]);
            #pragma unroll
            for (int rr = 1; rr < CSIZE; rr++)
                st_remote(la, (uint32_t)((rank + rr) & (CSIZE-1)), e);
        }
        __syncwarp();
        cluster_sync_();
    }

    // ---- final cost: sum EA.*(G2*EB*G) + sum EA.*(G*EB*G2) ----
    float csum = 0.0f;

    acc[0]=acc[1]=acc[2]=0.0f;
    mm1x3(G2 + ig*PITCH, Bt + j0*PITCH, acc);    // U = G2 * EB
    Uw[0]=acc[0]; Uw[1]=acc[1]; Uw[2]=acc[2];
    __syncwarp();
    acc[0]=acc[1]=acc[2]=0.0f;
    mm1x3(Ur, Gb, acc);                          // T1 = U * G
    #pragma unroll
    for (int c = 0; c < 3; c++) csum += ea[c] * acc[c];
    __syncwarp();

    acc[0]=acc[1]=acc[2]=0.0f;
    mm1x3(Ga, Bt + j0*PITCH, acc);               // U = G * EB
    Uw[0]=acc[0]; Uw[1]=acc[1]; Uw[2]=acc[2];
    __syncwarp();
    acc[0]=acc[1]=acc[2]=0.0f;
    mm1x3(Ur, G2 + j0*PITCH, acc);               // T2 = U * G2
    #pragma unroll
    for (int c = 0; c < 3; c++) csum += ea[c] * acc[c];

    csum = block_sum(csum, red);

    // cluster reduction into rank 0
    if (tid == 0) {
        if (rank == 0) red[16] = csum;
        else st_remote(smem_u32(&red[16 + rank]), 0u, csum);
    }
    cluster_sync_();
    if (rank == 0 && tid == 0)
        out[batch] = red[16] + red[17] + red[18] + red[19];
}

extern "C" void kernel_launch(void* const* d_in, const int* in_sizes, int n_in,
                              void* d_out, int out_size) {
    const float* img_pred   = (const float*)d_in[0];
    const float* img_target = (const float*)d_in[1];
    const float* cm         = (const float*)d_in[2];
    float* out = (float*)d_out;

    const int B = in_sizes[0] / (3 * NPIX);   // 32
    sinkhorn_kernel<<<B * CSIZE, NTHR>>>(img_pred, img_target, cm, out);
}